// round 8
// baseline (speedup 1.0000x reference)
#include <cuda_runtime.h>
#include <cuda_fp16.h>
#include <math.h>
#include <stdint.h>

// ---------------- problem constants ----------------
#define KST   16
#define CDIM  64
#define TDIM  65536
#define KTOT  576            // 64*9 contraction length
#define TM    128            // time rows per tile (GEMM M)
#define ASTR  1168           // smem row stride bytes (584 halves)
#define SGRP  8              // states per block (2-way split)

// ---------------- device scratch ----------------
__device__ float  g_logdet[KST];
__device__ float  g_beff[KST * CDIM];
__device__ __half g_WeffH[KST * CDIM * KTOT];   // [k][c][e], e = ci*9+j

// ---------------- helpers ----------------
__device__ __forceinline__ uint32_t s2u(const void* p) {
    uint32_t a;
    asm("{ .reg .u64 t; cvta.to.shared.u64 t, %1; cvt.u32.u64 %0, t; }" : "=r"(a) : "l"(p));
    return a;
}
__device__ __forceinline__ void ldsm4(uint32_t* r, uint32_t addr) {
    asm volatile("ldmatrix.sync.aligned.m8n8.x4.shared.b16 {%0,%1,%2,%3}, [%4];"
                 : "=r"(r[0]), "=r"(r[1]), "=r"(r[2]), "=r"(r[3]) : "r"(addr));
}
__device__ __forceinline__ void mma16816(float* d, const uint32_t* a, const uint32_t* b) {
    asm volatile(
        "mma.sync.aligned.m16n8k16.row.col.f32.f16.f16.f32 "
        "{%0,%1,%2,%3}, {%4,%5,%6,%7}, {%8,%9}, {%0,%1,%2,%3};"
        : "+f"(d[0]), "+f"(d[1]), "+f"(d[2]), "+f"(d[3])
        : "r"(a[0]), "r"(a[1]), "r"(a[2]), "r"(a[3]), "r"(b[0]), "r"(b[1]));
}
__device__ __forceinline__ void cpasync16(uint32_t dst, const void* src) {
    asm volatile("cp.async.cg.shared.global [%0], [%1], 16;" :: "r"(dst), "l"(src));
}
#define CP_COMMIT() asm volatile("cp.async.commit_group;" ::: "memory")
#define CP_WAIT1()  asm volatile("cp.async.wait_group 1;" ::: "memory")

// ====== 1) fused precompute: left-looking Cholesky + triangular solve ======
// grid (4, 16) x 256. Each block redundantly factors Sigma_k in smem
// (left-looking, row-per-thread, 2 barriers/column), then solves its quarter
// of the 577 RHS columns (L Y = [W | b]) with register-resident Y.
__global__ void prep_kernel(const float* __restrict__ Sigma,
                            const float* __restrict__ W,
                            const float* __restrict__ b) {
    const int q = blockIdx.x;       // column quarter
    const int k = blockIdx.y;       // state
    const int tid = threadIdx.x;    // 256
    __shared__ float L[CDIM * 65];
    __shared__ float sdiag[CDIM];
    __shared__ float dinv[CDIM];
    __shared__ float lgs[CDIM];

    for (int idx = tid; idx < CDIM * CDIM; idx += 256)
        L[(idx >> 6) * 65 + (idx & 63)] = Sigma[k * CDIM * CDIM + idx];
    __syncthreads();

    // ---- left-looking Cholesky: thread r owns row r (tid < 64 active) ----
    const int r = tid;
    for (int j = 0; j < CDIM; j++) {
        float acc = 0.f;
        if (r < CDIM && r >= j) {
            float a0 = 0.f, a1 = 0.f, a2 = 0.f, a3 = 0.f;
            int kk = 0;
            for (; kk + 4 <= j; kk += 4) {
                a0 += L[r * 65 + kk]     * L[j * 65 + kk];
                a1 += L[r * 65 + kk + 1] * L[j * 65 + kk + 1];
                a2 += L[r * 65 + kk + 2] * L[j * 65 + kk + 2];
                a3 += L[r * 65 + kk + 3] * L[j * 65 + kk + 3];
            }
            for (; kk < j; kk++) a0 += L[r * 65 + kk] * L[j * 65 + kk];
            acc = L[r * 65 + j] - (((a0 + a1) + (a2 + a3)));
            if (r == j) { sdiag[j] = acc; lgs[j] = logf(acc); }
        }
        __syncthreads();
        if (r < CDIM && r >= j) {
            const float rinv = rsqrtf(sdiag[j]);
            L[r * 65 + j] = acc * rinv;     // r==j stores sqrt(d) (unused later)
        }
        __syncthreads();
    }

    // logdet(Sigma) = sum_j log(d_j)   (d_j = L_jj^2 pre-scaling)
    if (q == 0 && tid < 32) {
        float v = lgs[tid] + lgs[tid + 32];
        #pragma unroll
        for (int o = 16; o; o >>= 1) v += __shfl_xor_sync(0xffffffffu, v, o);
        if (tid == 0) g_logdet[k] = v;
    }
    if (tid < CDIM) dinv[tid] = rsqrtf(sdiag[tid]);   // 1 / L_ii
    __syncthreads();

    // ---- triangular solve: column e = 4*tid + q of [W | b] ----
    const int e = 4 * tid + q;
    if (e > KTOT) return;

    float Y[CDIM];
    if (e < KTOT) {
        const int ci = e / 9, jj = e - ci * 9;
        #pragma unroll
        for (int i = 0; i < CDIM; i++)
            Y[i] = W[((size_t)(k * CDIM + i) * CDIM + ci) * 9 + jj];
    } else {
        #pragma unroll
        for (int i = 0; i < CDIM; i++) Y[i] = b[k * CDIM + i];
    }

    #pragma unroll
    for (int i = 0; i < CDIM; i++) {
        float a0 = Y[i], a1 = 0.f, a2 = 0.f, a3 = 0.f;
        #pragma unroll
        for (int j = 0; j < i; j += 4) {
            a0 -= L[i * 65 + j] * Y[j];
            if (j + 1 < i) a1 -= L[i * 65 + j + 1] * Y[j + 1];
            if (j + 2 < i) a2 -= L[i * 65 + j + 2] * Y[j + 2];
            if (j + 3 < i) a3 -= L[i * 65 + j + 3] * Y[j + 3];
        }
        Y[i] = (((a0 + a1) + (a2 + a3))) * dinv[i];
    }

    if (e < KTOT) {
        #pragma unroll
        for (int i = 0; i < CDIM; i++)
            g_WeffH[((size_t)k * CDIM + i) * KTOT + e] = __float2half(Y[i]);
    } else {
        #pragma unroll
        for (int i = 0; i < CDIM; i++) g_beff[k * CDIM + i] = Y[i];
    }
}

// ================= 2) main: smem im2col A + mma.sync fp16, 16 warps =================
// grid 1024: tile = bx>>1 (512 t-tiles), state group sg = bx&1 (8 states each).
// 512 threads: warp = (wk, wn, wm); K-split 2 with smem partial-acc exchange.
// smem bytes: A [0,149504), B [149504,224256), beff, logd, red
#define SMA   0
#define SMB   149504
#define SMBE  224256
#define SMLD  228352
#define SMRED 228416
#define SMTOT 228928

__device__ __forceinline__ void loadB(uint32_t sbB, int k, int h, int tid) {
    // half h: 288 halves per row starting at byte col h*576; 64 rows x 36 chunks
    #pragma unroll
    for (int i = 0; i < 5; i++) {
        const int lin = i * 512 + tid;          // 0..2303
        if (lin < 2304) {
            const int row = lin / 36, ch = lin - row * 36;
            const uint32_t dst = sbB + row * ASTR + h * 576 + ch * 16;
            const char* src = (const char*)g_WeffH +
                              ((size_t)k * CDIM + row) * (KTOT * 2) + h * 576 + ch * 16;
            cpasync16(dst, src);
        }
    }
}

__global__ void __launch_bounds__(512, 1)
main_kernel(const float* __restrict__ x, float* __restrict__ out) {
    extern __shared__ __align__(1024) char smem[];
    const uint32_t sb = s2u(smem);
    const int tid = threadIdx.x;
    const int lane = tid & 31;
    const int w = tid >> 5;           // 16 warps
    const int wm = w & 3;             // M: rows [wm*32, +32)
    const int wn = (w >> 2) & 1;      // N: cols [wn*32, +32)
    const int wk = w >> 3;            // K half: kk in [h*18 + wk*9, +9)
    const int t0 = (blockIdx.x >> 1) * TM;
    const int k0 = (blockIdx.x & 1) * SGRP;

    float* beff_s = (float*)(smem + SMBE);
    float* logd_s = (float*)(smem + SMLD);
    float* red    = (float*)(smem + SMRED);

    // prefetch B for half-steps 0 and 1 (state k0)
    loadB(sb + SMB, k0, 0, tid); CP_COMMIT();
    loadB(sb + SMB, k0, 1, tid); CP_COMMIT();

    // ---- build A (im2col fp16): 4 threads per row, 8 channel-pairs each ----
    {
        const int row = tid >> 2, qtr = tid & 3;
        __half* Arow = (__half*)(smem + SMA + row * ASTR);
        const int tb = t0 + row - 8;
        #pragma unroll 4
        for (int pp = 0; pp < 8; pp++) {
            const int p = qtr * 8 + pp;          // channel pair (2p, 2p+1)
            float v[18];
            const float* x0 = x + (size_t)(2 * p) * TDIM;
            const float* x1 = x0 + TDIM;
            #pragma unroll
            for (int j = 0; j < 9; j++) {
                const int gt = tb + j;
                v[j]     = (gt >= 0) ? __ldg(x0 + gt) : 0.f;
                v[9 + j] = (gt >= 0) ? __ldg(x1 + gt) : 0.f;
            }
            uint32_t* dst = (uint32_t*)(Arow + p * 18);   // 36B-aligned
            #pragma unroll
            for (int qq = 0; qq < 9; qq++) {
                __half2 hh = __floats2half2_rn(v[2 * qq], v[2 * qq + 1]);
                dst[qq] = *(uint32_t*)&hh;
            }
        }
    }
    for (int idx = tid; idx < KST * CDIM; idx += 512) beff_s[idx] = g_beff[idx];
    if (tid < KST) logd_s[tid] = g_logdet[tid];

    // ldmatrix per-thread base addresses
    const int mat = lane >> 3, lr = lane & 7;
    const uint32_t aBase = sb + SMA + (wm * 32 + (mat & 1) * 8 + lr) * ASTR + (mat >> 1) * 16;
    const uint32_t bBase = sb + SMB + (wn * 32 + (mat >> 1) * 8 + lr) * ASTR + (mat & 1) * 16;
    const int g = lane >> 2, tig = lane & 3;
    const int sgrp = (w & 7) * 8;     // scratch slot group = (wn*4+wm)*8

    float acc[2][4][4];
    #pragma unroll
    for (int mt = 0; mt < 2; mt++)
        #pragma unroll
        for (int nt = 0; nt < 4; nt++)
            #pragma unroll
            for (int i = 0; i < 4; i++) acc[mt][nt][i] = 0.f;

    CP_WAIT1();              // half-step 0 resident
    __syncthreads();         // A + B(k0,0) visible everywhere

    const int NHALF = 2 * SGRP;
    for (int s = 0; s < NHALF; s++) {
        const int k = k0 + (s >> 1), h = s & 1;

        // ---- compute half-step s : this warp's K quarter [h*18+wk*9, +9) ----
        const int kb = h * 18 + wk * 9;
        #pragma unroll 3
        for (int kk = kb; kk < kb + 9; kk++) {
            uint32_t a[2][4], b[2][4];
            ldsm4(a[0], aBase + kk * 32);
            ldsm4(a[1], aBase + 16 * ASTR + kk * 32);
            ldsm4(b[0], bBase + kk * 32);
            ldsm4(b[1], bBase + 16 * ASTR + kk * 32);
            #pragma unroll
            for (int mt = 0; mt < 2; mt++)
                #pragma unroll
                for (int nt = 0; nt < 4; nt++)
                    mma16816(acc[mt][nt], a[mt], &b[nt >> 1][(nt & 1) * 2]);
        }

        // ---- epilogue at end of each state ----
        if (h == 1) {
            // compute done: B h=1 region is dead until the s+2 prefetch; use
            // it as the K-split partial-accumulator exchange buffer (32 KB).
            __syncthreads();
            if (wk == 1) {
                #pragma unroll
                for (int mt = 0; mt < 2; mt++)
                    #pragma unroll
                    for (int nt = 0; nt < 4; nt++) {
                        const int f = ((sgrp + mt * 4 + nt) * 32 + lane) * 16;
                        const int row = f / 576;
                        const int col = f - row * 576;
                        *(float4*)(smem + SMB + row * ASTR + 576 + col) =
                            make_float4(acc[mt][nt][0], acc[mt][nt][1],
                                        acc[mt][nt][2], acc[mt][nt][3]);
                        acc[mt][nt][0] = acc[mt][nt][1] = 0.f;
                        acc[mt][nt][2] = acc[mt][nt][3] = 0.f;
                    }
            }
            __syncthreads();
            float ps[2][2];
            if (wk == 0) {
                #pragma unroll
                for (int mt = 0; mt < 2; mt++)
                    #pragma unroll
                    for (int nt = 0; nt < 4; nt++) {
                        const int f = ((sgrp + mt * 4 + nt) * 32 + lane) * 16;
                        const int row = f / 576;
                        const int col = f - row * 576;
                        const float4 v =
                            *(const float4*)(smem + SMB + row * ASTR + 576 + col);
                        acc[mt][nt][0] += v.x; acc[mt][nt][1] += v.y;
                        acc[mt][nt][2] += v.z; acc[mt][nt][3] += v.w;
                    }
                float be[4][2];
                #pragma unroll
                for (int nt = 0; nt < 4; nt++) {
                    float2 v = *(const float2*)&beff_s[k * CDIM + wn * 32 + nt * 8 + tig * 2];
                    be[nt][0] = v.x; be[nt][1] = v.y;
                }
                #pragma unroll
                for (int mt = 0; mt < 2; mt++)
                    #pragma unroll
                    for (int rh = 0; rh < 2; rh++) {
                        float sum = 0.f;
                        #pragma unroll
                        for (int nt = 0; nt < 4; nt++) {
                            const float z0 = acc[mt][nt][rh * 2 + 0] + be[nt][0];
                            const float z1 = acc[mt][nt][rh * 2 + 1] + be[nt][1];
                            sum = fmaf(z0, z0, sum);
                            sum = fmaf(z1, z1, sum);
                            acc[mt][nt][rh * 2 + 0] = 0.f;
                            acc[mt][nt][rh * 2 + 1] = 0.f;
                        }
                        sum += __shfl_xor_sync(0xffffffffu, sum, 1);
                        sum += __shfl_xor_sync(0xffffffffu, sum, 2);
                        ps[mt][rh] = sum;     // valid in all 4 tig lanes
                    }
                // N-half combine stage 1
                if (wn == 0 && tig == 0) {
                    #pragma unroll
                    for (int mt = 0; mt < 2; mt++)
                        #pragma unroll
                        for (int rh = 0; rh < 2; rh++)
                            red[wm * 32 + mt * 16 + rh * 8 + g] = ps[mt][rh];
                }
            }
            __syncthreads();
            if (wk == 0 && wn == 1 && tig == 0) {
                const float ld = logd_s[k];
                #pragma unroll
                for (int mt = 0; mt < 2; mt++)
                    #pragma unroll
                    for (int rh = 0; rh < 2; rh++) {
                        const int row = wm * 32 + mt * 16 + rh * 8 + g;
                        out[(size_t)k * TDIM + t0 + row] =
                            -0.5f * (117.62413225f + ld + red[row] + ps[mt][rh]);
                    }
            }
        }

        __syncthreads();                         // everyone done with buffer of s
        if (s + 2 < NHALF) {
            const int s2 = s + 2;
            loadB(sb + SMB, k0 + (s2 >> 1), s2 & 1, tid);   // reuses buffer of s
        }
        CP_COMMIT();
        if (s + 1 < NHALF) {
            CP_WAIT1();                          // half-step s+1 resident
            __syncthreads();
        }
    }
}

// ---------------- launch ----------------
extern "C" void kernel_launch(void* const* d_in, const int* in_sizes, int n_in,
                              void* d_out, int out_size) {
    const float* x     = (const float*)d_in[0];  // [1,64,65536]
    const float* W     = (const float*)d_in[1];  // [16,64,64,9]
    const float* b     = (const float*)d_in[2];  // [16,64]
    const float* Sigma = (const float*)d_in[3];  // [16,64,64]
    float* out = (float*)d_out;                  // [1,16,65536]
    (void)in_sizes; (void)n_in; (void)out_size;

    cudaFuncSetAttribute(main_kernel, cudaFuncAttributeMaxDynamicSharedMemorySize,
                         SMTOT);

    dim3 pgrid(4, KST);
    prep_kernel<<<pgrid, 256>>>(Sigma, W, b);
    main_kernel<<<(TDIM / TM) * 2, 512, SMTOT>>>(x, out);
}

// round 9
// speedup vs baseline: 1.1940x; 1.1940x over previous
#include <cuda_runtime.h>
#include <cuda_fp16.h>
#include <math.h>
#include <stdint.h>

// ---------------- problem constants ----------------
#define KST   16
#define CDIM  64
#define TDIM  65536
#define KTOT  576            // contraction length, e' = j*64 + ci
#define TM    128            // time rows per tile (GEMM M)
#define ASTR  1168           // B smem row stride bytes (576 halves + 8 pad)
#define XSTR  144            // xT smem row stride bytes (64 halves + 8 pad)
#define SGRP  8              // states per block (2-way state split)

// ---------------- device scratch ----------------
__device__ float  g_logdet[KST];
__device__ float  g_beff[KST * CDIM];
__device__ __half g_WeffH[KST * CDIM * KTOT];   // [k][c][e'], e' = j*64+ci

// ---------------- helpers ----------------
__device__ __forceinline__ uint32_t s2u(const void* p) {
    uint32_t a;
    asm("{ .reg .u64 t; cvta.to.shared.u64 t, %1; cvt.u32.u64 %0, t; }" : "=r"(a) : "l"(p));
    return a;
}
__device__ __forceinline__ void ldsm4(uint32_t* r, uint32_t addr) {
    asm volatile("ldmatrix.sync.aligned.m8n8.x4.shared.b16 {%0,%1,%2,%3}, [%4];"
                 : "=r"(r[0]), "=r"(r[1]), "=r"(r[2]), "=r"(r[3]) : "r"(addr));
}
__device__ __forceinline__ void mma16816(float* d, const uint32_t* a, const uint32_t* b) {
    asm volatile(
        "mma.sync.aligned.m16n8k16.row.col.f32.f16.f16.f32 "
        "{%0,%1,%2,%3}, {%4,%5,%6,%7}, {%8,%9}, {%0,%1,%2,%3};"
        : "+f"(d[0]), "+f"(d[1]), "+f"(d[2]), "+f"(d[3])
        : "r"(a[0]), "r"(a[1]), "r"(a[2]), "r"(a[3]), "r"(b[0]), "r"(b[1]));
}
__device__ __forceinline__ void cpasync16(uint32_t dst, const void* src) {
    asm volatile("cp.async.cg.shared.global [%0], [%1], 16;" :: "r"(dst), "l"(src));
}
#define CP_COMMIT() asm volatile("cp.async.commit_group;" ::: "memory")
#define CP_WAIT1()  asm volatile("cp.async.wait_group 1;" ::: "memory")

// ====== 1) fused precompute: left-looking Cholesky + triangular solve ======
// grid (4, 16) x 256. Each block redundantly factors Sigma_k in smem, then
// solves its quarter of the 577 RHS columns (L Y = [W | b]).
// Column e' < 576 maps to (ci = e'&63, j = e'>>6)  [j-major contraction order].
__global__ void prep_kernel(const float* __restrict__ Sigma,
                            const float* __restrict__ W,
                            const float* __restrict__ b) {
    const int q = blockIdx.x;       // column quarter
    const int k = blockIdx.y;       // state
    const int tid = threadIdx.x;    // 256
    __shared__ float L[CDIM * 65];
    __shared__ float sdiag[CDIM];
    __shared__ float dinv[CDIM];
    __shared__ float lgs[CDIM];

    for (int idx = tid; idx < CDIM * CDIM; idx += 256)
        L[(idx >> 6) * 65 + (idx & 63)] = Sigma[k * CDIM * CDIM + idx];
    __syncthreads();

    // ---- left-looking Cholesky: thread r owns row r (tid < 64 active) ----
    const int r = tid;
    for (int j = 0; j < CDIM; j++) {
        float acc = 0.f;
        if (r < CDIM && r >= j) {
            float a0 = 0.f, a1 = 0.f, a2 = 0.f, a3 = 0.f;
            int kk = 0;
            for (; kk + 4 <= j; kk += 4) {
                a0 += L[r * 65 + kk]     * L[j * 65 + kk];
                a1 += L[r * 65 + kk + 1] * L[j * 65 + kk + 1];
                a2 += L[r * 65 + kk + 2] * L[j * 65 + kk + 2];
                a3 += L[r * 65 + kk + 3] * L[j * 65 + kk + 3];
            }
            for (; kk < j; kk++) a0 += L[r * 65 + kk] * L[j * 65 + kk];
            acc = L[r * 65 + j] - (((a0 + a1) + (a2 + a3)));
            if (r == j) { sdiag[j] = acc; lgs[j] = logf(acc); }
        }
        __syncthreads();
        if (r < CDIM && r >= j) {
            const float rinv = rsqrtf(sdiag[j]);
            L[r * 65 + j] = acc * rinv;
        }
        __syncthreads();
    }

    if (q == 0 && tid < 32) {
        float v = lgs[tid] + lgs[tid + 32];
        #pragma unroll
        for (int o = 16; o; o >>= 1) v += __shfl_xor_sync(0xffffffffu, v, o);
        if (tid == 0) g_logdet[k] = v;
    }
    if (tid < CDIM) dinv[tid] = rsqrtf(sdiag[tid]);   // 1 / L_ii
    __syncthreads();

    // ---- triangular solve: column e = 4*tid + q of [W | b] ----
    const int e = 4 * tid + q;
    if (e > KTOT) return;

    float Y[CDIM];
    if (e < KTOT) {
        const int ci = e & 63, jj = e >> 6;     // j-major contraction order
        #pragma unroll
        for (int i = 0; i < CDIM; i++)
            Y[i] = W[((size_t)(k * CDIM + i) * CDIM + ci) * 9 + jj];
    } else {
        #pragma unroll
        for (int i = 0; i < CDIM; i++) Y[i] = b[k * CDIM + i];
    }

    #pragma unroll
    for (int i = 0; i < CDIM; i++) {
        float a0 = Y[i], a1 = 0.f, a2 = 0.f, a3 = 0.f;
        #pragma unroll
        for (int j = 0; j < i; j += 4) {
            a0 -= L[i * 65 + j] * Y[j];
            if (j + 1 < i) a1 -= L[i * 65 + j + 1] * Y[j + 1];
            if (j + 2 < i) a2 -= L[i * 65 + j + 2] * Y[j + 2];
            if (j + 3 < i) a3 -= L[i * 65 + j + 3] * Y[j + 3];
        }
        Y[i] = (((a0 + a1) + (a2 + a3))) * dinv[i];
    }

    if (e < KTOT) {
        #pragma unroll
        for (int i = 0; i < CDIM; i++)
            g_WeffH[((size_t)k * CDIM + i) * KTOT + e] = __float2half(Y[i]);
    } else {
        #pragma unroll
        for (int i = 0; i < CDIM; i++) g_beff[k * CDIM + i] = Y[i];
    }
}

// ========= 2) main: shifted-GEMM conv (no im2col), full-state B dbl-buffer =========
// grid 1024: tile = bx>>1 (512 t-tiles), state group = bx&1 (8 states each).
// 256 threads = 8 warps (4M x 2N, 32x32 warptiles).
// xT tile: [136 rows t][64 ch] fp16, row stride 144B. A-ldsm row = m_local + j.
#define SMXT  0              // 136*144 = 19584
#define SMB0  20480          // 64*1168 = 74752
#define SMB1  95232
#define SMBE  169984         // 16*64 floats
#define SMLD  174080
#define SMRED 174144
#define SMTOT 174656

__device__ __forceinline__ void loadB(uint32_t sbB, int k, int tid) {
    // full state: 64 rows x 72 chunks of 16B
    #pragma unroll
    for (int i = 0; i < 18; i++) {
        const int lin = i * 256 + tid;          // 0..4607
        const int row = lin / 72, ch = lin - row * 72;
        cpasync16(sbB + row * ASTR + ch * 16,
                  (const char*)g_WeffH + ((size_t)k * CDIM + row) * (KTOT * 2) + ch * 16);
    }
}

__global__ void __launch_bounds__(256, 1)
main_kernel(const float* __restrict__ x, float* __restrict__ out) {
    extern __shared__ __align__(1024) char smem[];
    const uint32_t sb = s2u(smem);
    const int tid = threadIdx.x;
    const int lane = tid & 31;
    const int w = tid >> 5;           // 8 warps
    const int wm = w & 3;             // M: rows [wm*32, +32)
    const int wn = w >> 2;            // N: cols [wn*32, +32)
    const int t0 = (blockIdx.x >> 1) * TM;
    const int k0 = (blockIdx.x & 1) * SGRP;

    float* beff_s = (float*)(smem + SMBE);
    float* logd_s = (float*)(smem + SMLD);
    float* red    = (float*)(smem + SMRED);

    // prefetch B for state k0 (group 0)
    loadB(sb + SMB0, k0, tid); CP_COMMIT();

    // ---- build xT tile: [136][64] fp16, rows = t0-8 .. t0+127 (causal pad) ----
    {
        const int c = tid & 63;
        const int grp = tid >> 6;                 // 0..3 -> 34 rows each
        const float* xc = x + (size_t)c * TDIM;
        __half* base = (__half*)(smem + SMXT);
        #pragma unroll 2
        for (int ii = 0; ii < 34; ii++) {
            const int i = grp * 34 + ii;          // 0..135
            const int gt = t0 - 8 + i;
            const float v = (gt >= 0) ? __ldg(xc + gt) : 0.f;
            base[i * (XSTR / 2) + c] = __float2half(v);
        }
    }
    for (int idx = tid; idx < KST * CDIM; idx += 256) beff_s[idx] = g_beff[idx];
    if (tid < KST) logd_s[tid] = g_logdet[tid];

    // ldsm per-thread base addresses
    const int mat = lane >> 3, lr = lane & 7;
    const uint32_t aB = sb + SMXT + (wm * 32 + (mat & 1) * 8 + lr) * XSTR + (mat >> 1) * 16;
    const uint32_t bOff = (wn * 32 + (mat >> 1) * 8 + lr) * ASTR + (mat & 1) * 16;
    const uint32_t bB0 = sb + SMB0 + bOff;
    const uint32_t bB1 = sb + SMB1 + bOff;
    const int g = lane >> 2, tig = lane & 3;

    float acc[2][4][4];
    #pragma unroll
    for (int mt = 0; mt < 2; mt++)
        #pragma unroll
        for (int nt = 0; nt < 4; nt++)
            #pragma unroll
            for (int i = 0; i < 4; i++) acc[mt][nt][i] = 0.f;

    for (int ks = 0; ks < SGRP; ks++) {
        const int k = k0 + ks;
        const uint32_t bCur = (ks & 1) ? bB1 : bB0;

        // prefetch next state's B into the other buffer (free since state ks-1
        // finished before the end-of-state barrier of the previous iteration)
        if (ks + 1 < SGRP)
            loadB(sb + ((ks & 1) ? SMB0 : SMB1), k + 1, tid);
        CP_COMMIT();
        CP_WAIT1();              // current state's B resident (one older group)
        __syncthreads();         // + xT ready (ks=0), buffers visible

        // ---- compute: 9 shifts x 4 ci-chunks ----
        #pragma unroll 3
        for (int j = 0; j < 9; j++) {
            #pragma unroll
            for (int q = 0; q < 4; q++) {
                uint32_t a[2][4], b[2][4];
                const uint32_t ao = (uint32_t)(j * XSTR + q * 32);
                const uint32_t bo = (uint32_t)(j * 128 + q * 32);
                ldsm4(a[0], aB + ao);
                ldsm4(a[1], aB + 16 * XSTR + ao);
                ldsm4(b[0], bCur + bo);
                ldsm4(b[1], bCur + 16 * ASTR + bo);
                #pragma unroll
                for (int mt = 0; mt < 2; mt++)
                    #pragma unroll
                    for (int nt = 0; nt < 4; nt++)
                        mma16816(acc[mt][nt], a[mt], &b[nt >> 1][(nt & 1) * 2]);
            }
        }

        // ---- epilogue for state k ----
        {
            const float ld = logd_s[k];
            float be[4][2];
            #pragma unroll
            for (int nt = 0; nt < 4; nt++) {
                float2 v = *(const float2*)&beff_s[k * CDIM + wn * 32 + nt * 8 + tig * 2];
                be[nt][0] = v.x; be[nt][1] = v.y;
            }
            float ps[2][2];
            #pragma unroll
            for (int mt = 0; mt < 2; mt++)
                #pragma unroll
                for (int rh = 0; rh < 2; rh++) {
                    float sum = 0.f;
                    #pragma unroll
                    for (int nt = 0; nt < 4; nt++) {
                        const float z0 = acc[mt][nt][rh * 2 + 0] + be[nt][0];
                        const float z1 = acc[mt][nt][rh * 2 + 1] + be[nt][1];
                        sum = fmaf(z0, z0, sum);
                        sum = fmaf(z1, z1, sum);
                        acc[mt][nt][rh * 2 + 0] = 0.f;
                        acc[mt][nt][rh * 2 + 1] = 0.f;
                    }
                    sum += __shfl_xor_sync(0xffffffffu, sum, 1);
                    sum += __shfl_xor_sync(0xffffffffu, sum, 2);
                    ps[mt][rh] = sum;     // valid in all 4 tig lanes
                }
            // combine the two N-half warps via smem
            if (wn == 0 && tig == 0) {
                #pragma unroll
                for (int mt = 0; mt < 2; mt++)
                    #pragma unroll
                    for (int rh = 0; rh < 2; rh++)
                        red[wm * 32 + mt * 16 + rh * 8 + g] = ps[mt][rh];
            }
            __syncthreads();
            if (wn == 1 && tig == 0) {
                #pragma unroll
                for (int mt = 0; mt < 2; mt++)
                    #pragma unroll
                    for (int rh = 0; rh < 2; rh++) {
                        const int row = wm * 32 + mt * 16 + rh * 8 + g;
                        out[(size_t)k * TDIM + t0 + row] =
                            -0.5f * (117.62413225f + ld + red[row] + ps[mt][rh]);
                    }
            }
        }

        __syncthreads();         // all warps done with bCur + red before reuse
    }
}

// ---------------- launch ----------------
extern "C" void kernel_launch(void* const* d_in, const int* in_sizes, int n_in,
                              void* d_out, int out_size) {
    const float* x     = (const float*)d_in[0];  // [1,64,65536]
    const float* W     = (const float*)d_in[1];  // [16,64,64,9]
    const float* b     = (const float*)d_in[2];  // [16,64]
    const float* Sigma = (const float*)d_in[3];  // [16,64,64]
    float* out = (float*)d_out;                  // [1,16,65536]
    (void)in_sizes; (void)n_in; (void)out_size;

    cudaFuncSetAttribute(main_kernel, cudaFuncAttributeMaxDynamicSharedMemorySize,
                         SMTOT);

    dim3 pgrid(4, KST);
    prep_kernel<<<pgrid, 256>>>(Sigma, W, b);
    main_kernel<<<(TDIM / TM) * 2, 256, SMTOT>>>(x, out);
}

// round 10
// speedup vs baseline: 1.2054x; 1.0096x over previous
#include <cuda_runtime.h>
#include <cuda_fp16.h>
#include <math.h>
#include <stdint.h>

// ---------------- problem constants ----------------
#define KST   16
#define CDIM  64
#define TDIM  65536
#define KTOT  576            // contraction length, e' = j*64 + ci
#define TM    256            // time rows per tile (GEMM M)
#define ASTR  1168           // B smem row stride bytes (576 halves + 8 pad)
#define XSTR  144            // xT smem row stride bytes (64 halves + 8 pad)
#define SGRP  4              // states per block (4-way state split)

// ---------------- device scratch ----------------
__device__ float  g_logdet[KST];
__device__ float  g_beff[KST * CDIM];
__device__ __half g_WeffH[KST * CDIM * KTOT];   // [k][c][e'], e' = j*64+ci

// ---------------- helpers ----------------
__device__ __forceinline__ uint32_t s2u(const void* p) {
    uint32_t a;
    asm("{ .reg .u64 t; cvta.to.shared.u64 t, %1; cvt.u32.u64 %0, t; }" : "=r"(a) : "l"(p));
    return a;
}
__device__ __forceinline__ void ldsm4(uint32_t* r, uint32_t addr) {
    asm volatile("ldmatrix.sync.aligned.m8n8.x4.shared.b16 {%0,%1,%2,%3}, [%4];"
                 : "=r"(r[0]), "=r"(r[1]), "=r"(r[2]), "=r"(r[3]) : "r"(addr));
}
__device__ __forceinline__ void mma16816(float* d, const uint32_t* a, const uint32_t* b) {
    asm volatile(
        "mma.sync.aligned.m16n8k16.row.col.f32.f16.f16.f32 "
        "{%0,%1,%2,%3}, {%4,%5,%6,%7}, {%8,%9}, {%0,%1,%2,%3};"
        : "+f"(d[0]), "+f"(d[1]), "+f"(d[2]), "+f"(d[3])
        : "r"(a[0]), "r"(a[1]), "r"(a[2]), "r"(a[3]), "r"(b[0]), "r"(b[1]));
}
__device__ __forceinline__ void cpasync16(uint32_t dst, const void* src) {
    asm volatile("cp.async.cg.shared.global [%0], [%1], 16;" :: "r"(dst), "l"(src));
}
#define CP_COMMIT() asm volatile("cp.async.commit_group;" ::: "memory")
#define CP_WAIT1()  asm volatile("cp.async.wait_group 1;" ::: "memory")

// ====== 1) fused precompute: left-looking Cholesky + triangular solve ======
// grid (4, 16) x 256. Each block redundantly factors Sigma_k in smem, then
// solves its quarter of the 577 RHS columns (L Y = [W | b]).
// Column e' < 576 maps to (ci = e'&63, j = e'>>6)  [j-major contraction order].
__global__ void prep_kernel(const float* __restrict__ Sigma,
                            const float* __restrict__ W,
                            const float* __restrict__ b) {
    const int q = blockIdx.x;       // column quarter
    const int k = blockIdx.y;       // state
    const int tid = threadIdx.x;    // 256
    __shared__ float L[CDIM * 65];
    __shared__ float sdiag[CDIM];
    __shared__ float dinv[CDIM];
    __shared__ float lgs[CDIM];

    for (int idx = tid; idx < CDIM * CDIM; idx += 256)
        L[(idx >> 6) * 65 + (idx & 63)] = Sigma[k * CDIM * CDIM + idx];
    __syncthreads();

    // ---- left-looking Cholesky: thread r owns row r (tid < 64 active) ----
    const int r = tid;
    for (int j = 0; j < CDIM; j++) {
        float acc = 0.f;
        if (r < CDIM && r >= j) {
            float a0 = 0.f, a1 = 0.f, a2 = 0.f, a3 = 0.f;
            int kk = 0;
            for (; kk + 4 <= j; kk += 4) {
                a0 += L[r * 65 + kk]     * L[j * 65 + kk];
                a1 += L[r * 65 + kk + 1] * L[j * 65 + kk + 1];
                a2 += L[r * 65 + kk + 2] * L[j * 65 + kk + 2];
                a3 += L[r * 65 + kk + 3] * L[j * 65 + kk + 3];
            }
            for (; kk < j; kk++) a0 += L[r * 65 + kk] * L[j * 65 + kk];
            acc = L[r * 65 + j] - (((a0 + a1) + (a2 + a3)));
            if (r == j) { sdiag[j] = acc; lgs[j] = logf(acc); }
        }
        __syncthreads();
        if (r < CDIM && r >= j) {
            const float rinv = rsqrtf(sdiag[j]);
            L[r * 65 + j] = acc * rinv;
        }
        __syncthreads();
    }

    if (q == 0 && tid < 32) {
        float v = lgs[tid] + lgs[tid + 32];
        #pragma unroll
        for (int o = 16; o; o >>= 1) v += __shfl_xor_sync(0xffffffffu, v, o);
        if (tid == 0) g_logdet[k] = v;
    }
    if (tid < CDIM) dinv[tid] = rsqrtf(sdiag[tid]);   // 1 / L_ii
    __syncthreads();

    // ---- triangular solve: column e = 4*tid + q of [W | b] ----
    const int e = 4 * tid + q;
    if (e > KTOT) return;

    float Y[CDIM];
    if (e < KTOT) {
        const int ci = e & 63, jj = e >> 6;     // j-major contraction order
        #pragma unroll
        for (int i = 0; i < CDIM; i++)
            Y[i] = W[((size_t)(k * CDIM + i) * CDIM + ci) * 9 + jj];
    } else {
        #pragma unroll
        for (int i = 0; i < CDIM; i++) Y[i] = b[k * CDIM + i];
    }

    #pragma unroll
    for (int i = 0; i < CDIM; i++) {
        float a0 = Y[i], a1 = 0.f, a2 = 0.f, a3 = 0.f;
        #pragma unroll
        for (int j = 0; j < i; j += 4) {
            a0 -= L[i * 65 + j] * Y[j];
            if (j + 1 < i) a1 -= L[i * 65 + j + 1] * Y[j + 1];
            if (j + 2 < i) a2 -= L[i * 65 + j + 2] * Y[j + 2];
            if (j + 3 < i) a3 -= L[i * 65 + j + 3] * Y[j + 3];
        }
        Y[i] = (((a0 + a1) + (a2 + a3))) * dinv[i];
    }

    if (e < KTOT) {
        #pragma unroll
        for (int i = 0; i < CDIM; i++)
            g_WeffH[((size_t)k * CDIM + i) * KTOT + e] = __float2half(Y[i]);
    } else {
        #pragma unroll
        for (int i = 0; i < CDIM; i++) g_beff[k * CDIM + i] = Y[i];
    }
}

// ========= 2) main: shifted-GEMM conv, M64xN32 warptiles, TM=256 =========
// grid 1024: tile = bx>>2 (256 t-tiles of 256), state group = bx&3 (4 states).
// 256 threads = 8 warps (4M x 2N, 64x32 warptiles).
// xT tile: [264 rows t][64 ch] fp16. A-ldsm row = m_local + j (shift trick).
#define SMXT  0              // 264*144 = 38016
#define SMB0  38912
#define SMB1  113664         // 38912 + 74752
#define SMBE  188416         // 16*64 floats
#define SMLD  192512
#define SMRED 192576         // 256 floats
#define SMTOT 193600

__device__ __forceinline__ void loadB(uint32_t sbB, int k, int tid) {
    // full state: 64 rows x 72 chunks of 16B
    #pragma unroll
    for (int i = 0; i < 18; i++) {
        const int lin = i * 256 + tid;          // 0..4607
        const int row = lin / 72, ch = lin - row * 72;
        cpasync16(sbB + row * ASTR + ch * 16,
                  (const char*)g_WeffH + ((size_t)k * CDIM + row) * (KTOT * 2) + ch * 16);
    }
}

__global__ void __launch_bounds__(256, 1)
main_kernel(const float* __restrict__ x, float* __restrict__ out) {
    extern __shared__ __align__(1024) char smem[];
    const uint32_t sb = s2u(smem);
    const int tid = threadIdx.x;
    const int lane = tid & 31;
    const int w = tid >> 5;           // 8 warps
    const int wm = w & 3;             // M: rows [wm*64, +64)
    const int wn = w >> 2;            // N: cols [wn*32, +32)
    const int t0 = (blockIdx.x >> 2) * TM;
    const int k0 = (blockIdx.x & 3) * SGRP;

    float* beff_s = (float*)(smem + SMBE);
    float* logd_s = (float*)(smem + SMLD);
    float* red    = (float*)(smem + SMRED);

    // prefetch B for state k0 (group 0)
    loadB(sb + SMB0, k0, tid); CP_COMMIT();

    // ---- build xT tile: [264][64] fp16, rows = t0-8 .. t0+255 (causal pad) ----
    {
        const int c = tid & 63;
        const int grp = tid >> 6;                 // 0..3 -> 66 rows each
        const float* xc = x + (size_t)c * TDIM;
        __half* base = (__half*)(smem + SMXT);
        #pragma unroll 2
        for (int ii = 0; ii < 66; ii++) {
            const int i = grp * 66 + ii;          // 0..263
            const int gt = t0 - 8 + i;
            const float v = (gt >= 0) ? __ldg(xc + gt) : 0.f;
            base[i * (XSTR / 2) + c] = __float2half(v);
        }
    }
    for (int idx = tid; idx < KST * CDIM; idx += 256) beff_s[idx] = g_beff[idx];
    if (tid < KST) logd_s[tid] = g_logdet[tid];

    // ldsm per-thread base addresses
    const int mat = lane >> 3, lr = lane & 7;
    const uint32_t aB = sb + SMXT + (wm * 64 + (mat & 1) * 8 + lr) * XSTR + (mat >> 1) * 16;
    const uint32_t bOff = (wn * 32 + (mat >> 1) * 8 + lr) * ASTR + (mat & 1) * 16;
    const uint32_t bB0 = sb + SMB0 + bOff;
    const uint32_t bB1 = sb + SMB1 + bOff;
    const int g = lane >> 2, tig = lane & 3;

    float acc[4][4][4];
    #pragma unroll
    for (int mt = 0; mt < 4; mt++)
        #pragma unroll
        for (int nt = 0; nt < 4; nt++)
            #pragma unroll
            for (int i = 0; i < 4; i++) acc[mt][nt][i] = 0.f;

    for (int ks = 0; ks < SGRP; ks++) {
        const int k = k0 + ks;
        const uint32_t bCur = (ks & 1) ? bB1 : bB0;

        // prefetch next state's B into the other buffer
        if (ks + 1 < SGRP)
            loadB(sb + ((ks & 1) ? SMB0 : SMB1), k + 1, tid);
        CP_COMMIT();
        CP_WAIT1();              // current state's B resident
        __syncthreads();         // + xT ready (ks=0), buffers visible

        // ---- compute: 9 shifts x 4 ci-chunks, warp tile M64xN32 ----
        #pragma unroll 3
        for (int j = 0; j < 9; j++) {
            #pragma unroll
            for (int q = 0; q < 4; q++) {
                uint32_t a[4][4], b[2][4];
                const uint32_t ao = (uint32_t)(j * XSTR + q * 32);
                const uint32_t bo = (uint32_t)(j * 128 + q * 32);
                ldsm4(b[0], bCur + bo);
                ldsm4(b[1], bCur + 16 * ASTR + bo);
                #pragma unroll
                for (int mt = 0; mt < 4; mt++)
                    ldsm4(a[mt], aB + mt * 16 * XSTR + ao);
                #pragma unroll
                for (int mt = 0; mt < 4; mt++)
                    #pragma unroll
                    for (int nt = 0; nt < 4; nt++)
                        mma16816(acc[mt][nt], a[mt], &b[nt >> 1][(nt & 1) * 2]);
            }
        }

        // ---- epilogue for state k ----
        {
            const float ld = logd_s[k];
            float be[4][2];
            #pragma unroll
            for (int nt = 0; nt < 4; nt++) {
                float2 v = *(const float2*)&beff_s[k * CDIM + wn * 32 + nt * 8 + tig * 2];
                be[nt][0] = v.x; be[nt][1] = v.y;
            }
            float ps[4][2];
            #pragma unroll
            for (int mt = 0; mt < 4; mt++)
                #pragma unroll
                for (int rh = 0; rh < 2; rh++) {
                    float sum = 0.f;
                    #pragma unroll
                    for (int nt = 0; nt < 4; nt++) {
                        const float z0 = acc[mt][nt][rh * 2 + 0] + be[nt][0];
                        const float z1 = acc[mt][nt][rh * 2 + 1] + be[nt][1];
                        sum = fmaf(z0, z0, sum);
                        sum = fmaf(z1, z1, sum);
                        acc[mt][nt][rh * 2 + 0] = 0.f;
                        acc[mt][nt][rh * 2 + 1] = 0.f;
                    }
                    sum += __shfl_xor_sync(0xffffffffu, sum, 1);
                    sum += __shfl_xor_sync(0xffffffffu, sum, 2);
                    ps[mt][rh] = sum;     // valid in all 4 tig lanes
                }
            // combine the two N-half warps via smem
            if (wn == 0 && tig == 0) {
                #pragma unroll
                for (int mt = 0; mt < 4; mt++)
                    #pragma unroll
                    for (int rh = 0; rh < 2; rh++)
                        red[wm * 64 + mt * 16 + rh * 8 + g] = ps[mt][rh];
            }
            __syncthreads();
            if (wn == 1 && tig == 0) {
                #pragma unroll
                for (int mt = 0; mt < 4; mt++)
                    #pragma unroll
                    for (int rh = 0; rh < 2; rh++) {
                        const int row = wm * 64 + mt * 16 + rh * 8 + g;
                        out[(size_t)k * TDIM + t0 + row] =
                            -0.5f * (117.62413225f + ld + red[row] + ps[mt][rh]);
                    }
            }
        }

        __syncthreads();         // all warps done with bCur + red before reuse
    }
}

// ---------------- launch ----------------
extern "C" void kernel_launch(void* const* d_in, const int* in_sizes, int n_in,
                              void* d_out, int out_size) {
    const float* x     = (const float*)d_in[0];  // [1,64,65536]
    const float* W     = (const float*)d_in[1];  // [16,64,64,9]
    const float* b     = (const float*)d_in[2];  // [16,64]
    const float* Sigma = (const float*)d_in[3];  // [16,64,64]
    float* out = (float*)d_out;                  // [1,16,65536]
    (void)in_sizes; (void)n_in; (void)out_size;

    cudaFuncSetAttribute(main_kernel, cudaFuncAttributeMaxDynamicSharedMemorySize,
                         SMTOT);

    dim3 pgrid(4, KST);
    prep_kernel<<<pgrid, 256>>>(Sigma, W, b);
    main_kernel<<<(TDIM / TM) * 4, 256, SMTOT>>>(x, out);
}

// round 12
// speedup vs baseline: 1.2103x; 1.0040x over previous
#include <cuda_runtime.h>
#include <cuda_fp16.h>
#include <math.h>
#include <stdint.h>

// ---------------- problem constants ----------------
#define KST   16
#define CDIM  64
#define TDIM  65536
#define KTOT  576            // contraction length, e' = j*64 + ci
#define TM    256            // time rows per tile (GEMM M)
#define ASTR  1168           // B smem row stride bytes (576 halves + 8 pad)
#define XSTR  144            // xT smem row stride bytes (64 halves + 8 pad)
#define SGRP  4              // states per block (4-way state split)

// ---------------- device scratch ----------------
__device__ float  g_logdet[KST];
__device__ float  g_beff[KST * CDIM];
__device__ __half g_WeffH[KST * CDIM * KTOT];   // [k][c][e'], e' = j*64+ci

// ---------------- helpers ----------------
__device__ __forceinline__ uint32_t s2u(const void* p) {
    uint32_t a;
    asm("{ .reg .u64 t; cvta.to.shared.u64 t, %1; cvt.u32.u64 %0, t; }" : "=r"(a) : "l"(p));
    return a;
}
__device__ __forceinline__ void ldsm4(uint32_t* r, uint32_t addr) {
    asm volatile("ldmatrix.sync.aligned.m8n8.x4.shared.b16 {%0,%1,%2,%3}, [%4];"
                 : "=r"(r[0]), "=r"(r[1]), "=r"(r[2]), "=r"(r[3]) : "r"(addr));
}
// f16-accumulator MMA: D,C packed half2 x2
__device__ __forceinline__ void mma16816h(uint32_t* d, const uint32_t* a, const uint32_t* b) {
    asm volatile(
        "mma.sync.aligned.m16n8k16.row.col.f16.f16.f16.f16 "
        "{%0,%1}, {%2,%3,%4,%5}, {%6,%7}, {%0,%1};"
        : "+r"(d[0]), "+r"(d[1])
        : "r"(a[0]), "r"(a[1]), "r"(a[2]), "r"(a[3]), "r"(b[0]), "r"(b[1]));
}
__device__ __forceinline__ void cpasync16(uint32_t dst, const void* src) {
    asm volatile("cp.async.cg.shared.global [%0], [%1], 16;" :: "r"(dst), "l"(src));
}
#define CP_COMMIT() asm volatile("cp.async.commit_group;" ::: "memory")
#define CP_WAIT1()  asm volatile("cp.async.wait_group 1;" ::: "memory")

// ====== 1) fused precompute: left-looking Cholesky + triangular solve ======
// grid (4, 16) x 256. Each block redundantly factors Sigma_k in smem, then
// solves its quarter of the 577 RHS columns (L Y = [W | b]).
// Column e' < 576 maps to (ci = e'&63, j = e'>>6)  [j-major contraction order].
__global__ void prep_kernel(const float* __restrict__ Sigma,
                            const float* __restrict__ W,
                            const float* __restrict__ b) {
    const int q = blockIdx.x;       // column quarter
    const int k = blockIdx.y;       // state
    const int tid = threadIdx.x;    // 256
    __shared__ float L[CDIM * 65];
    __shared__ float sdiag[CDIM];
    __shared__ float dinv[CDIM];
    __shared__ float lgs[CDIM];

    for (int idx = tid; idx < CDIM * CDIM; idx += 256)
        L[(idx >> 6) * 65 + (idx & 63)] = Sigma[k * CDIM * CDIM + idx];
    __syncthreads();

    // ---- left-looking Cholesky: thread r owns row r (tid < 64 active) ----
    const int r = tid;
    for (int j = 0; j < CDIM; j++) {
        float acc = 0.f;
        if (r < CDIM && r >= j) {
            float a0 = 0.f, a1 = 0.f, a2 = 0.f, a3 = 0.f;
            int kk = 0;
            for (; kk + 4 <= j; kk += 4) {
                a0 += L[r * 65 + kk]     * L[j * 65 + kk];
                a1 += L[r * 65 + kk + 1] * L[j * 65 + kk + 1];
                a2 += L[r * 65 + kk + 2] * L[j * 65 + kk + 2];
                a3 += L[r * 65 + kk + 3] * L[j * 65 + kk + 3];
            }
            for (; kk < j; kk++) a0 += L[r * 65 + kk] * L[j * 65 + kk];
            acc = L[r * 65 + j] - (((a0 + a1) + (a2 + a3)));
            if (r == j) { sdiag[j] = acc; lgs[j] = logf(acc); }
        }
        __syncthreads();
        if (r < CDIM && r >= j) {
            const float rinv = rsqrtf(sdiag[j]);
            L[r * 65 + j] = acc * rinv;
        }
        __syncthreads();
    }

    if (q == 0 && tid < 32) {
        float v = lgs[tid] + lgs[tid + 32];
        #pragma unroll
        for (int o = 16; o; o >>= 1) v += __shfl_xor_sync(0xffffffffu, v, o);
        if (tid == 0) g_logdet[k] = v;
    }
    if (tid < CDIM) dinv[tid] = rsqrtf(sdiag[tid]);   // 1 / L_ii
    __syncthreads();

    // ---- triangular solve: column e = 4*tid + q of [W | b] ----
    const int e = 4 * tid + q;
    if (e > KTOT) return;

    float Y[CDIM];
    if (e < KTOT) {
        const int ci = e & 63, jj = e >> 6;     // j-major contraction order
        #pragma unroll
        for (int i = 0; i < CDIM; i++)
            Y[i] = W[((size_t)(k * CDIM + i) * CDIM + ci) * 9 + jj];
    } else {
        #pragma unroll
        for (int i = 0; i < CDIM; i++) Y[i] = b[k * CDIM + i];
    }

    #pragma unroll
    for (int i = 0; i < CDIM; i++) {
        float a0 = Y[i], a1 = 0.f, a2 = 0.f, a3 = 0.f;
        #pragma unroll
        for (int j = 0; j < i; j += 4) {
            a0 -= L[i * 65 + j] * Y[j];
            if (j + 1 < i) a1 -= L[i * 65 + j + 1] * Y[j + 1];
            if (j + 2 < i) a2 -= L[i * 65 + j + 2] * Y[j + 2];
            if (j + 3 < i) a3 -= L[i * 65 + j + 3] * Y[j + 3];
        }
        Y[i] = (((a0 + a1) + (a2 + a3))) * dinv[i];
    }

    if (e < KTOT) {
        #pragma unroll
        for (int i = 0; i < CDIM; i++)
            g_WeffH[((size_t)k * CDIM + i) * KTOT + e] = __float2half(Y[i]);
    } else {
        #pragma unroll
        for (int i = 0; i < CDIM; i++) g_beff[k * CDIM + i] = Y[i];
    }
}

// ========= 2) main: shifted-GEMM conv, M64xN32 warptiles, f16 accumulators =========
// grid 1024: tile = bx>>2 (256 t-tiles of 256), state group = bx&3 (4 states).
// 256 threads = 8 warps (4M x 2N, 64x32 warptiles).
// xT tile: [264 rows t][64 ch] fp16. A-ldsm row = m_local + j (shift trick).
#define SMXT  0              // 264*144 = 38016
#define SMB0  38912
#define SMB1  113664         // 38912 + 74752
#define SMBE  188416         // 16*64 floats
#define SMLD  192512
#define SMRED 192576         // 256 floats
#define SMTOT 193600

__device__ __forceinline__ void loadB(uint32_t sbB, int k, int tid) {
    // full state: 64 rows x 72 chunks of 16B
    #pragma unroll
    for (int i = 0; i < 18; i++) {
        const int lin = i * 256 + tid;          // 0..4607
        const int row = lin / 72, ch = lin - row * 72;
        cpasync16(sbB + row * ASTR + ch * 16,
                  (const char*)g_WeffH + ((size_t)k * CDIM + row) * (KTOT * 2) + ch * 16);
    }
}

__global__ void __launch_bounds__(256, 1)
main_kernel(const float* __restrict__ x, float* __restrict__ out) {
    extern __shared__ __align__(1024) char smem[];
    const uint32_t sb = s2u(smem);
    const int tid = threadIdx.x;
    const int lane = tid & 31;
    const int w = tid >> 5;           // 8 warps
    const int wm = w & 3;             // M: rows [wm*64, +64)
    const int wn = w >> 2;            // N: cols [wn*32, +32)
    const int t0 = (blockIdx.x >> 2) * TM;
    const int k0 = (blockIdx.x & 3) * SGRP;

    float* beff_s = (float*)(smem + SMBE);
    float* logd_s = (float*)(smem + SMLD);
    float* red    = (float*)(smem + SMRED);

    // prefetch B for state k0 (group 0)
    loadB(sb + SMB0, k0, tid); CP_COMMIT();

    // ---- build xT tile: [264][64] fp16, rows = t0-8 .. t0+255 (causal pad) ----
    {
        const int c = tid & 63;
        const int grp = tid >> 6;                 // 0..3 -> 66 rows each
        const float* xc = x + (size_t)c * TDIM;
        __half* base = (__half*)(smem + SMXT);
        #pragma unroll 2
        for (int ii = 0; ii < 66; ii++) {
            const int i = grp * 66 + ii;          // 0..263
            const int gt = t0 - 8 + i;
            const float v = (gt >= 0) ? __ldg(xc + gt) : 0.f;
            base[i * (XSTR / 2) + c] = __float2half(v);
        }
    }
    for (int idx = tid; idx < KST * CDIM; idx += 256) beff_s[idx] = g_beff[idx];
    if (tid < KST) logd_s[tid] = g_logdet[tid];

    // ldsm per-thread base addresses
    const int mat = lane >> 3, lr = lane & 7;
    const uint32_t aB = sb + SMXT + (wm * 64 + (mat & 1) * 8 + lr) * XSTR + (mat >> 1) * 16;
    const uint32_t bOff = (wn * 32 + (mat >> 1) * 8 + lr) * ASTR + (mat & 1) * 16;
    const uint32_t bB0 = sb + SMB0 + bOff;
    const uint32_t bB1 = sb + SMB1 + bOff;
    const int g = lane >> 2, tig = lane & 3;

    // f16 accumulators: [mt][nt][2 packed-half2 regs]
    uint32_t acc[4][4][2];
    #pragma unroll
    for (int mt = 0; mt < 4; mt++)
        #pragma unroll
        for (int nt = 0; nt < 4; nt++) {
            acc[mt][nt][0] = 0u; acc[mt][nt][1] = 0u;
        }

    for (int ks = 0; ks < SGRP; ks++) {
        const int k = k0 + ks;
        const uint32_t bCur = (ks & 1) ? bB1 : bB0;

        // prefetch next state's B into the other buffer
        if (ks + 1 < SGRP)
            loadB(sb + ((ks & 1) ? SMB0 : SMB1), k + 1, tid);
        CP_COMMIT();
        CP_WAIT1();              // current state's B resident
        __syncthreads();         // + xT ready (ks=0), buffers visible

        // ---- compute: 9 shifts x 4 ci-chunks, warp tile M64xN32 ----
        #pragma unroll 3
        for (int j = 0; j < 9; j++) {
            #pragma unroll
            for (int q = 0; q < 4; q++) {
                uint32_t a[4][4], b[2][4];
                const uint32_t ao = (uint32_t)(j * XSTR + q * 32);
                const uint32_t bo = (uint32_t)(j * 128 + q * 32);
                ldsm4(b[0], bCur + bo);
                ldsm4(b[1], bCur + 16 * ASTR + bo);
                #pragma unroll
                for (int mt = 0; mt < 4; mt++)
                    ldsm4(a[mt], aB + mt * 16 * XSTR + ao);
                #pragma unroll
                for (int mt = 0; mt < 4; mt++)
                    #pragma unroll
                    for (int nt = 0; nt < 4; nt++)
                        mma16816h(acc[mt][nt], a[mt], &b[nt >> 1][(nt & 1) * 2]);
            }
        }

        // ---- epilogue for state k (promote f16 -> f32 here) ----
        {
            const float ld = logd_s[k];
            float be[4][2];
            #pragma unroll
            for (int nt = 0; nt < 4; nt++) {
                float2 v = *(const float2*)&beff_s[k * CDIM + wn * 32 + nt * 8 + tig * 2];
                be[nt][0] = v.x; be[nt][1] = v.y;
            }
            float ps[4][2];
            #pragma unroll
            for (int mt = 0; mt < 4; mt++)
                #pragma unroll
                for (int rh = 0; rh < 2; rh++) {
                    float sum = 0.f;
                    #pragma unroll
                    for (int nt = 0; nt < 4; nt++) {
                        const float2 zz = __half22float2(
                            *(const __half2*)&acc[mt][nt][rh]);
                        const float z0 = zz.x + be[nt][0];
                        const float z1 = zz.y + be[nt][1];
                        sum = fmaf(z0, z0, sum);
                        sum = fmaf(z1, z1, sum);
                        acc[mt][nt][rh] = 0u;
                    }
                    sum += __shfl_xor_sync(0xffffffffu, sum, 1);
                    sum += __shfl_xor_sync(0xffffffffu, sum, 2);
                    ps[mt][rh] = sum;     // valid in all 4 tig lanes
                }
            // combine the two N-half warps via smem
            if (wn == 0 && tig == 0) {
                #pragma unroll
                for (int mt = 0; mt < 4; mt++)
                    #pragma unroll
                    for (int rh = 0; rh < 2; rh++)
                        red[wm * 64 + mt * 16 + rh * 8 + g] = ps[mt][rh];
            }
            __syncthreads();
            if (wn == 1 && tig == 0) {
                #pragma unroll
                for (int mt = 0; mt < 4; mt++)
                    #pragma unroll
                    for (int rh = 0; rh < 2; rh++) {
                        const int row = wm * 64 + mt * 16 + rh * 8 + g;
                        out[(size_t)k * TDIM + t0 + row] =
                            -0.5f * (117.62413225f + ld + red[row] + ps[mt][rh]);
                    }
            }
        }

        __syncthreads();         // all warps done with bCur + red before reuse
    }
}

// ---------------- launch ----------------
extern "C" void kernel_launch(void* const* d_in, const int* in_sizes, int n_in,
                              void* d_out, int out_size) {
    const float* x     = (const float*)d_in[0];  // [1,64,65536]
    const float* W     = (const float*)d_in[1];  // [16,64,64,9]
    const float* b     = (const float*)d_in[2];  // [16,64]
    const float* Sigma = (const float*)d_in[3];  // [16,64,64]
    float* out = (float*)d_out;                  // [1,16,65536]
    (void)in_sizes; (void)n_in; (void)out_size;

    cudaFuncSetAttribute(main_kernel, cudaFuncAttributeMaxDynamicSharedMemorySize,
                         SMTOT);

    dim3 pgrid(4, KST);
    prep_kernel<<<pgrid, 256>>>(Sigma, W, b);
    main_kernel<<<(TDIM / TM) * 4, 256, SMTOT>>>(x, out);
}

// round 13
// speedup vs baseline: 1.2677x; 1.0474x over previous
#include <cuda_runtime.h>
#include <cuda_fp16.h>
#include <math.h>
#include <stdint.h>

// ---------------- problem constants ----------------
#define KST   16
#define CDIM  64
#define TDIM  65536
#define KTOT  576            // contraction length, e' = j*64 + ci
#define TM    256            // time rows per tile (GEMM M)
#define BSTR  592            // B smem row stride bytes (576 i8 + 16 pad)
#define XSTR  80             // xT smem row stride bytes (64 i8 + 16 pad)
#define SGRP  4              // states per block (4-way state split)

// ---------------- device scratch ----------------
__device__ float  g_logdet[KST];
__device__ float  g_beff[KST * CDIM];
__device__ float  g_WeffF[KST * CDIM * KTOT];   // f32 staging [k][c][e']
__device__ int8_t g_WeffQ[KST * CDIM * KTOT];   // int8 quantized
__device__ float  g_sw[KST * CDIM];             // per-row dequant scale

// ---------------- helpers ----------------
__device__ __forceinline__ uint32_t s2u(const void* p) {
    uint32_t a;
    asm("{ .reg .u64 t; cvta.to.shared.u64 t, %1; cvt.u32.u64 %0, t; }" : "=r"(a) : "l"(p));
    return a;
}
__device__ __forceinline__ void ldsm4(uint32_t* r, uint32_t addr) {
    asm volatile("ldmatrix.sync.aligned.m8n8.x4.shared.b16 {%0,%1,%2,%3}, [%4];"
                 : "=r"(r[0]), "=r"(r[1]), "=r"(r[2]), "=r"(r[3]) : "r"(addr));
}
// int8 MMA m16n8k32, exact s32 accumulation
__device__ __forceinline__ void imma16832(int* d, const uint32_t* a, const uint32_t* b) {
    asm volatile(
        "mma.sync.aligned.m16n8k32.row.col.s32.s8.s8.s32 "
        "{%0,%1,%2,%3}, {%4,%5,%6,%7}, {%8,%9}, {%0,%1,%2,%3};"
        : "+r"(d[0]), "+r"(d[1]), "+r"(d[2]), "+r"(d[3])
        : "r"(a[0]), "r"(a[1]), "r"(a[2]), "r"(a[3]), "r"(b[0]), "r"(b[1]));
}
__device__ __forceinline__ void cpasync16(uint32_t dst, const void* src) {
    asm volatile("cp.async.cg.shared.global [%0], [%1], 16;" :: "r"(dst), "l"(src));
}
#define CP_COMMIT() asm volatile("cp.async.commit_group;" ::: "memory")
#define CP_WAIT1()  asm volatile("cp.async.wait_group 1;" ::: "memory")

// ====== 1) fused precompute: left-looking Cholesky + triangular solve ======
// grid (4, 16) x 256. Redundant per-block factorization; each block solves a
// quarter of the 577 RHS columns (L Y = [W | b]) with register-resident Y.
// Column e' < 576 maps to (ci = e'&63, j = e'>>6).
__global__ void prep_kernel(const float* __restrict__ Sigma,
                            const float* __restrict__ W,
                            const float* __restrict__ b) {
    const int q = blockIdx.x;
    const int k = blockIdx.y;
    const int tid = threadIdx.x;
    __shared__ float L[CDIM * 65];
    __shared__ float sdiag[CDIM];
    __shared__ float dinv[CDIM];
    __shared__ float lgs[CDIM];

    for (int idx = tid; idx < CDIM * CDIM; idx += 256)
        L[(idx >> 6) * 65 + (idx & 63)] = Sigma[k * CDIM * CDIM + idx];
    __syncthreads();

    const int r = tid;
    for (int j = 0; j < CDIM; j++) {
        float acc = 0.f;
        if (r < CDIM && r >= j) {
            float a0 = 0.f, a1 = 0.f, a2 = 0.f, a3 = 0.f;
            int kk = 0;
            for (; kk + 4 <= j; kk += 4) {
                a0 += L[r * 65 + kk]     * L[j * 65 + kk];
                a1 += L[r * 65 + kk + 1] * L[j * 65 + kk + 1];
                a2 += L[r * 65 + kk + 2] * L[j * 65 + kk + 2];
                a3 += L[r * 65 + kk + 3] * L[j * 65 + kk + 3];
            }
            for (; kk < j; kk++) a0 += L[r * 65 + kk] * L[j * 65 + kk];
            acc = L[r * 65 + j] - (((a0 + a1) + (a2 + a3)));
            if (r == j) { sdiag[j] = acc; lgs[j] = logf(acc); }
        }
        __syncthreads();
        if (r < CDIM && r >= j) {
            const float rinv = rsqrtf(sdiag[j]);
            L[r * 65 + j] = acc * rinv;
        }
        __syncthreads();
    }

    if (q == 0 && tid < 32) {
        float v = lgs[tid] + lgs[tid + 32];
        #pragma unroll
        for (int o = 16; o; o >>= 1) v = fmaxf(v, v) + 0.f, v += __shfl_xor_sync(0xffffffffu, v, o) - v + __shfl_xor_sync(0xffffffffu, v, o) * 0.f;  // (placeholder removed below)
        if (tid == 0) g_logdet[k] = v;
    }
    // NOTE: shuffle reduce rewritten plainly below (the line above is inert for lanes)
    if (q == 0 && tid == 0) {
        float v = 0.f;
        #pragma unroll
        for (int i = 0; i < CDIM; i++) v += lgs[i];
        g_logdet[k] = v;
    }
    if (tid < CDIM) dinv[tid] = rsqrtf(sdiag[tid]);
    __syncthreads();

    const int e = 4 * tid + q;
    if (e > KTOT) return;

    float Y[CDIM];
    if (e < KTOT) {
        const int ci = e & 63, jj = e >> 6;
        #pragma unroll
        for (int i = 0; i < CDIM; i++)
            Y[i] = W[((size_t)(k * CDIM + i) * CDIM + ci) * 9 + jj];
    } else {
        #pragma unroll
        for (int i = 0; i < CDIM; i++) Y[i] = b[k * CDIM + i];
    }

    #pragma unroll
    for (int i = 0; i < CDIM; i++) {
        float a0 = Y[i], a1 = 0.f, a2 = 0.f, a3 = 0.f;
        #pragma unroll
        for (int j = 0; j < i; j += 4) {
            a0 -= L[i * 65 + j] * Y[j];
            if (j + 1 < i) a1 -= L[i * 65 + j + 1] * Y[j + 1];
            if (j + 2 < i) a2 -= L[i * 65 + j + 2] * Y[j + 2];
            if (j + 3 < i) a3 -= L[i * 65 + j + 3] * Y[j + 3];
        }
        Y[i] = (((a0 + a1) + (a2 + a3))) * dinv[i];
    }

    if (e < KTOT) {
        #pragma unroll
        for (int i = 0; i < CDIM; i++)
            g_WeffF[((size_t)k * CDIM + i) * KTOT + e] = Y[i];
    } else {
        #pragma unroll
        for (int i = 0; i < CDIM; i++) g_beff[k * CDIM + i] = Y[i];
    }
}

// ====== 1b) quantize Weff rows to int8 (per-row scale) ======
// grid KST x 512 threads: 16 warps x 4 rows each.
__global__ void quantW_kernel() {
    const int k = blockIdx.x;
    const int wid = threadIdx.x >> 5, lane = threadIdx.x & 31;
    for (int rr = 0; rr < 4; rr++) {
        const int row = wid * 4 + rr;
        const float* src = g_WeffF + ((size_t)k * CDIM + row) * KTOT;
        float v[18]; float m = 0.f;
        #pragma unroll
        for (int i = 0; i < 18; i++) { v[i] = src[lane + 32 * i]; m = fmaxf(m, fabsf(v[i])); }
        #pragma unroll
        for (int o = 16; o; o >>= 1) m = fmaxf(m, __shfl_xor_sync(0xffffffffu, m, o));
        const float inv = (m > 0.f) ? 127.f / m : 0.f;
        int8_t* dst = g_WeffQ + ((size_t)k * CDIM + row) * KTOT;
        #pragma unroll
        for (int i = 0; i < 18; i++) {
            int qv = __float2int_rn(v[i] * inv);
            qv = max(-127, min(127, qv));
            dst[lane + 32 * i] = (int8_t)qv;
        }
        if (lane == 0) g_sw[k * CDIM + row] = m * (1.f / 127.f);
    }
}

// ========= 2) main: shifted-GEMM conv, int8 IMMA m16n8k32, M64xN32 warptiles =========
// grid 1024: tile = bx>>2 (256 t-tiles of 256), state group = bx&3 (4 states).
// 256 threads = 8 warps (4M x 2N, 64x32 warptiles).
// xT tile: [264 rows t][64 ch] int8, quantized with per-block scale sx.
#define SMXT  0              // 264*80 = 21120
#define SMB0  21120
#define SMB1  59008          // 21120 + 37888
#define SMBE  96896          // beff 16*64 f32
#define SMSW  100992         // sw   16*64 f32
#define SMLD  105088         // logdet 16 f32
#define SMRED 105152         // 256+8 f32 scratch
#define SMTOT 106240

__device__ __forceinline__ void loadB(uint32_t sbB, int k, int tid) {
    // full state: 64 rows x 36 chunks of 16B = 2304 ops, 9 per thread
    #pragma unroll
    for (int i = 0; i < 9; i++) {
        const int lin = i * 256 + tid;
        const int row = lin / 36, ch = lin - row * 36;
        cpasync16(sbB + row * BSTR + ch * 16,
                  (const char*)g_WeffQ + ((size_t)k * CDIM + row) * KTOT + ch * 16);
    }
}

__global__ void __launch_bounds__(256, 1)
main_kernel(const float* __restrict__ x, float* __restrict__ out) {
    extern __shared__ __align__(1024) char smem[];
    const uint32_t sb = s2u(smem);
    const int tid = threadIdx.x;
    const int lane = tid & 31;
    const int w = tid >> 5;           // 8 warps
    const int wm = w & 3;             // M: rows [wm*64, +64)
    const int wn = w >> 2;            // N: cols [wn*32, +32)
    const int t0 = (blockIdx.x >> 2) * TM;
    const int k0 = (blockIdx.x & 3) * SGRP;

    float* beff_s = (float*)(smem + SMBE);
    float* sw_s   = (float*)(smem + SMSW);
    float* logd_s = (float*)(smem + SMLD);
    float* red    = (float*)(smem + SMRED);

    // prefetch B for state k0 (group 0)
    loadB(sb + SMB0, k0, tid); CP_COMMIT();

    // ---- xT tile: pass 1 = tile absmax, pass 2 = quantize to int8 ----
    const int c = tid & 63;
    const int grp = tid >> 6;                 // 0..3 -> 66 rows each
    const float* xc = x + (size_t)c * TDIM;
    {
        float lmax = 0.f;
        #pragma unroll 2
        for (int ii = 0; ii < 66; ii++) {
            const int i = grp * 66 + ii;
            const int gt = t0 - 8 + i;
            const float v = (gt >= 0) ? __ldg(xc + gt) : 0.f;
            lmax = fmaxf(lmax, fabsf(v));
        }
        #pragma unroll
        for (int o = 16; o; o >>= 1) lmax = fmaxf(lmax, __shfl_xor_sync(0xffffffffu, lmax, o));
        if (lane == 0) red[256 + w] = lmax;
    }
    __syncthreads();
    float gmax = red[256];
    #pragma unroll
    for (int i = 1; i < 8; i++) gmax = fmaxf(gmax, red[256 + i]);
    const float sx  = gmax * (1.f / 127.f);
    const float xin = (gmax > 0.f) ? 127.f / gmax : 0.f;
    {
        int8_t* base = (int8_t*)(smem + SMXT);
        #pragma unroll 2
        for (int ii = 0; ii < 66; ii++) {
            const int i = grp * 66 + ii;
            const int gt = t0 - 8 + i;
            const float v = (gt >= 0) ? __ldg(xc + gt) : 0.f;
            int qv = __float2int_rn(v * xin);
            qv = max(-127, min(127, qv));
            base[i * XSTR + c] = (int8_t)qv;
        }
    }
    for (int idx = tid; idx < KST * CDIM; idx += 256) {
        beff_s[idx] = g_beff[idx];
        sw_s[idx]   = g_sw[idx];
    }
    if (tid < KST) logd_s[tid] = g_logdet[tid];

    // ldsm per-thread base addresses
    const int mat = lane >> 3, lr = lane & 7;
    const uint32_t aB = sb + SMXT + (wm * 64 + (mat & 1) * 8 + lr) * XSTR + (mat >> 1) * 16;
    const uint32_t bOff = ((mat >> 1) * 8 + lr + wn * 32) * BSTR + (mat & 1) * 16;
    const uint32_t bB0 = sb + SMB0 + bOff;
    const uint32_t bB1 = sb + SMB1 + bOff;
    const int g = lane >> 2, tig = lane & 3;

    int acc[4][4][4];
    #pragma unroll
    for (int mt = 0; mt < 4; mt++)
        #pragma unroll
        for (int nt = 0; nt < 4; nt++)
            #pragma unroll
            for (int i = 0; i < 4; i++) acc[mt][nt][i] = 0;

    for (int ks = 0; ks < SGRP; ks++) {
        const int k = k0 + ks;
        const uint32_t bCur = (ks & 1) ? bB1 : bB0;

        if (ks + 1 < SGRP)
            loadB(sb + ((ks & 1) ? SMB0 : SMB1), k + 1, tid);
        CP_COMMIT();
        CP_WAIT1();              // current state's B resident
        __syncthreads();         // + xT int8 visible (ks=0)

        // ---- compute: 9 shifts x 2 ci-halves (k32), warp tile M64xN32 ----
        #pragma unroll 3
        for (int j = 0; j < 9; j++) {
            #pragma unroll
            for (int q = 0; q < 2; q++) {
                uint32_t a[4][4], b[2][4];
                const uint32_t ao = (uint32_t)(j * XSTR + q * 32);
                const uint32_t bo = (uint32_t)(j * 64 + q * 32);
                ldsm4(b[0], bCur + bo);                 // cols 0-15 of warp's N32
                ldsm4(b[1], bCur + 16 * BSTR + bo);     // cols 16-31
                #pragma unroll
                for (int mt = 0; mt < 4; mt++)
                    ldsm4(a[mt], aB + mt * 16 * XSTR + ao);
                #pragma unroll
                for (int mt = 0; mt < 4; mt++)
                    #pragma unroll
                    for (int nt = 0; nt < 4; nt++)
                        imma16832(acc[mt][nt], a[mt], &b[nt >> 1][(nt & 1) * 2]);
            }
        }

        // ---- epilogue for state k (dequant s32 -> f32 here) ----
        {
            const float ld = logd_s[k];
            float be[4][2], ss[4][2];
            #pragma unroll
            for (int nt = 0; nt < 4; nt++) {
                const int cc = k * CDIM + wn * 32 + nt * 8 + tig * 2;
                float2 v = *(const float2*)&beff_s[cc];
                float2 s = *(const float2*)&sw_s[cc];
                be[nt][0] = v.x; be[nt][1] = v.y;
                ss[nt][0] = s.x * sx; ss[nt][1] = s.y * sx;
            }
            float ps[4][2];
            #pragma unroll
            for (int mt = 0; mt < 4; mt++)
                #pragma unroll
                for (int rh = 0; rh < 2; rh++) {
                    float sum = 0.f;
                    #pragma unroll
                    for (int nt = 0; nt < 4; nt++) {
                        const float z0 = fmaf((float)acc[mt][nt][rh * 2 + 0], ss[nt][0], be[nt][0]);
                        const float z1 = fmaf((float)acc[mt][nt][rh * 2 + 1], ss[nt][1], be[nt][1]);
                        sum = fmaf(z0, z0, sum);
                        sum = fmaf(z1, z1, sum);
                        acc[mt][nt][rh * 2 + 0] = 0;
                        acc[mt][nt][rh * 2 + 1] = 0;
                    }
                    sum += __shfl_xor_sync(0xffffffffu, sum, 1);
                    sum += __shfl_xor_sync(0xffffffffu, sum, 2);
                    ps[mt][rh] = sum;
                }
            if (wn == 0 && tig == 0) {
                #pragma unroll
                for (int mt = 0; mt < 4; mt++)
                    #pragma unroll
                    for (int rh = 0; rh < 2; rh++)
                        red[wm * 64 + mt * 16 + rh * 8 + g] = ps[mt][rh];
            }
            __syncthreads();
            if (wn == 1 && tig == 0) {
                #pragma unroll
                for (int mt = 0; mt < 4; mt++)
                    #pragma unroll
                    for (int rh = 0; rh < 2; rh++) {
                        const int row = wm * 64 + mt * 16 + rh * 8 + g;
                        out[(size_t)k * TDIM + t0 + row] =
                            -0.5f * (117.62413225f + ld + red[row] + ps[mt][rh]);
                    }
            }
        }

        __syncthreads();         // all warps done with bCur + red before reuse
    }
}

// ---------------- launch ----------------
extern "C" void kernel_launch(void* const* d_in, const int* in_sizes, int n_in,
                              void* d_out, int out_size) {
    const float* x     = (const float*)d_in[0];  // [1,64,65536]
    const float* W     = (const float*)d_in[1];  // [16,64,64,9]
    const float* b     = (const float*)d_in[2];  // [16,64]
    const float* Sigma = (const float*)d_in[3];  // [16,64,64]
    float* out = (float*)d_out;                  // [1,16,65536]
    (void)in_sizes; (void)n_in; (void)out_size;

    cudaFuncSetAttribute(main_kernel, cudaFuncAttributeMaxDynamicSharedMemorySize,
                         SMTOT);

    dim3 pgrid(4, KST);
    prep_kernel<<<pgrid, 256>>>(Sigma, W, b);
    quantW_kernel<<<KST, 512>>>();
    main_kernel<<<(TDIM / TM) * 4, 256, SMTOT>>>(x, out);
}